// round 1
// baseline (speedup 1.0000x reference)
#include <cuda_runtime.h>

#define N_NODES 50000
#define N_EDGES 800000
#define N_LABEL 200000
#define FEAT 128
#define HID 32
#define HEADS 8
#define H1 256   // HEADS*HID

// ---------------- scratch (device globals; no allocation) ----------------
__device__ __align__(16) float g_h0 [N_NODES * HID];   // node_lin output
__device__ __align__(16) float g_xs1[N_NODES * H1];    // conv1 source projection
__device__ __align__(16) float g_as1[N_NODES * HEADS];
__device__ __align__(16) float g_ad1[N_NODES * HEADS];
__device__ __align__(16) float g_den1[N_NODES * HEADS];
__device__ __align__(16) float g_e1 [N_EDGES * HEADS];
__device__ __align__(16) float g_out1[N_NODES * H1];   // conv1 accum -> h1 (in-place relu+bias)
__device__ __align__(16) float g_xs2[N_NODES * HID];
__device__ __align__(16) float g_as2[N_NODES];
__device__ __align__(16) float g_ad2[N_NODES];
__device__ __align__(16) float g_den2[N_NODES];
__device__ __align__(16) float g_e2 [N_EDGES];
__device__ __align__(16) float g_out2[N_NODES * HID];
__device__ __align__(16) float g_v1d[HID * HEADS];     // w1d folded with a1d
__device__ __align__(16) float g_v2d[H1];              // w2d folded with a2d

// ---------------- helpers ----------------
__device__ __forceinline__ void red_add_v4(float* addr, float4 v) {
    asm volatile("red.global.add.v4.f32 [%0], {%1,%2,%3,%4};"
                 :: "l"(addr), "f"(v.x), "f"(v.y), "f"(v.z), "f"(v.w)
                 : "memory");
}

__device__ __forceinline__ float lrelu_exp(float a) {
    float l = a > 0.f ? a : 0.2f * a;
    return expf(l);
}

// ---------------- K_zero: clear accumulators ----------------
__global__ void k_zero() {
    int idx = blockIdx.x * blockDim.x + threadIdx.x;
    int stride = gridDim.x * blockDim.x;
    for (int i = idx; i < N_NODES * H1;    i += stride) g_out1[i] = 0.f;
    for (int i = idx; i < N_NODES * HID;   i += stride) g_out2[i] = 0.f;
    for (int i = idx; i < N_NODES * HEADS; i += stride) g_den1[i] = 0.f;
    for (int i = idx; i < N_NODES;         i += stride) g_den2[i] = 0.f;
}

// ---------------- K_prep: fold dst projections with attention vectors ----------------
// v1d[k][h] = sum_c w1d[k, h*HID+c] * a1d[h, c]      (k < HID)
// v2d[k]    = sum_c w2d[k, c]      * a2d[0, c]       (k < H1)
__global__ void k_prep(const float* __restrict__ w1d, const float* __restrict__ a1d,
                       const float* __restrict__ w2d, const float* __restrict__ a2d) {
    int tid = threadIdx.x;  // 256 threads
    {
        int k = tid >> 3, h = tid & 7;  // k<32, h<8
        float s = 0.f;
        #pragma unroll
        for (int c = 0; c < HID; c++) s += w1d[k * H1 + h * HID + c] * a1d[h * HID + c];
        g_v1d[k * HEADS + h] = s;
    }
    {
        int k = tid;  // k < 256
        float s = 0.f;
        #pragma unroll
        for (int c = 0; c < HID; c++) s += w2d[k * HID + c] * a2d[c];
        g_v2d[k] = s;
    }
}

// ---------------- K_lin: h0 = x @ lin_w + lin_b   [50000,128]x[128,32] ----------------
__global__ void k_lin(const float* __restrict__ x, const float* __restrict__ w,
                      const float* __restrict__ b) {
    __shared__ float Ws[FEAT * HID];   // 16KB
    __shared__ float Xs[8 * FEAT];     // 4KB
    int tid = threadIdx.x;  // 256
    for (int i = tid; i < FEAT * HID; i += 256) Ws[i] = w[i];
    int nb = blockIdx.x * 8;
    for (int i = tid; i < 8 * FEAT; i += 256) {
        int n = nb + (i >> 7);
        Xs[i] = (n < N_NODES) ? x[(long long)n * FEAT + (i & 127)] : 0.f;
    }
    __syncthreads();
    int c = tid & 31, i = tid >> 5;
    int n = nb + i;
    if (n < N_NODES) {
        float acc = b[c];
        #pragma unroll 8
        for (int k = 0; k < FEAT; k++) acc += Xs[i * FEAT + k] * Ws[k * HID + c];
        g_h0[n * HID + c] = acc;
    }
}

// ---------------- K_gemm1: xs1 = h0 @ w1s   [50000,32]x[32,256] ----------------
__global__ void k_gemm1(const float* __restrict__ w1s) {
    __shared__ float Hs[16 * HID];  // 2KB
    int tid = threadIdx.x;  // 256 = one output column per thread
    float wreg[HID];
    #pragma unroll
    for (int k = 0; k < HID; k++) wreg[k] = w1s[k * H1 + tid];
    int nb = blockIdx.x * 16;
    for (int i = tid; i < 16 * HID; i += 256) {
        int n = nb + (i >> 5);
        Hs[i] = (n < N_NODES) ? g_h0[n * HID + (i & 31)] : 0.f;
    }
    __syncthreads();
    #pragma unroll 4
    for (int i = 0; i < 16; i++) {
        int n = nb + i;
        if (n >= N_NODES) break;
        float acc = 0.f;
        #pragma unroll
        for (int k = 0; k < HID; k++) acc += Hs[i * HID + k] * wreg[k];
        g_xs1[n * H1 + tid] = acc;
    }
}

// ---------------- K_att1: per-node attention scalars for conv1 ----------------
// a_s1[n,h] = sum_c xs1[n, h*32+c] * a1s[h,c];  a_d1[n,h] = sum_k h0[n,k] * v1d[k,h]
__global__ void k_att1(const float* __restrict__ a1s) {
    int lane = threadIdx.x & 31;
    int n = blockIdx.x * 8 + (threadIdx.x >> 5);
    if (n >= N_NODES) return;
    float h0v = g_h0[n * HID + lane];
    #pragma unroll
    for (int h = 0; h < HEADS; h++) {
        float s = g_xs1[n * H1 + h * HID + lane] * a1s[h * HID + lane];
        float d = h0v * g_v1d[lane * HEADS + h];
        #pragma unroll
        for (int off = 16; off; off >>= 1) {
            s += __shfl_down_sync(0xffffffffu, s, off);
            d += __shfl_down_sync(0xffffffffu, d, off);
        }
        if (lane == 0) { g_as1[n * HEADS + h] = s; g_ad1[n * HEADS + h] = d; }
    }
}

// ---------------- K_edge1a: e = exp(lrelu(a_s[src]+a_d[dst])); denom += e ----------------
__global__ void k_edge1a(const int* __restrict__ ei) {
    int e = blockIdx.x * blockDim.x + threadIdx.x;
    if (e >= N_EDGES) return;
    int src = ei[e], dst = ei[N_EDGES + e];
    float4 s0 = *(const float4*)&g_as1[src * HEADS];
    float4 s1 = *(const float4*)&g_as1[src * HEADS + 4];
    float4 d0 = *(const float4*)&g_ad1[dst * HEADS];
    float4 d1 = *(const float4*)&g_ad1[dst * HEADS + 4];
    float4 E0 = make_float4(lrelu_exp(s0.x + d0.x), lrelu_exp(s0.y + d0.y),
                            lrelu_exp(s0.z + d0.z), lrelu_exp(s0.w + d0.w));
    float4 E1 = make_float4(lrelu_exp(s1.x + d1.x), lrelu_exp(s1.y + d1.y),
                            lrelu_exp(s1.z + d1.z), lrelu_exp(s1.w + d1.w));
    *(float4*)&g_e1[e * HEADS]     = E0;
    *(float4*)&g_e1[e * HEADS + 4] = E1;
    red_add_v4(&g_den1[dst * HEADS],     E0);
    red_add_v4(&g_den1[dst * HEADS + 4], E1);
}

// ---------------- K_scatter1: out1[dst] += xs1[src] * coef  (warp per edge, 256 ch) ----------------
__global__ void k_scatter1(const int* __restrict__ ei) {
    int lane = threadIdx.x & 31;
    int e = blockIdx.x * 8 + (threadIdx.x >> 5);
    if (e >= N_EDGES) return;
    int src = ei[e], dst = ei[N_EDGES + e];
    float coef = 0.f;
    if (lane < 8) coef = g_e1[e * HEADS + lane] / (g_den1[dst * HEADS + lane] + 1e-16f);
    #pragma unroll
    for (int it = 0; it < 2; it++) {
        int cbase = it * 128 + lane * 4;
        int h = cbase >> 5;
        float c = __shfl_sync(0xffffffffu, coef, h);
        float4 v = *(const float4*)&g_xs1[src * H1 + cbase];
        v.x *= c; v.y *= c; v.z *= c; v.w *= c;
        red_add_v4(&g_out1[dst * H1 + cbase], v);
    }
}

// ---------------- K_relu_ad2: h1 = relu(out1 + b1) in-place; a_d2[n] = h1[n]·v2d ----------------
__global__ void k_relu_ad2(const float* __restrict__ b1) {
    int n = blockIdx.x;
    int c = threadIdx.x;  // 256
    float v = g_out1[n * H1 + c] + b1[c];
    v = fmaxf(v, 0.f);
    g_out1[n * H1 + c] = v;
    float p = v * g_v2d[c];
    #pragma unroll
    for (int off = 16; off; off >>= 1) p += __shfl_down_sync(0xffffffffu, p, off);
    __shared__ float red[8];
    if ((c & 31) == 0) red[c >> 5] = p;
    __syncthreads();
    if (c < 8) {
        p = red[c];
        #pragma unroll
        for (int off = 4; off; off >>= 1) p += __shfl_down_sync(0x000000ffu, p, off);
        if (c == 0) g_ad2[n] = p;
    }
}

// ---------------- K_gemm2: xs2 = h1 @ w2s  [50000,256]x[256,32]; a_s2 = xs2·a2s ----------------
__global__ void k_gemm2(const float* __restrict__ w2s, const float* __restrict__ a2s) {
    __shared__ float Ws[H1 * HID];  // 32KB
    int tid = threadIdx.x;  // 256
    for (int i = tid; i < H1 * HID; i += 256) Ws[i] = w2s[i];
    __syncthreads();
    int lane = tid & 31;
    int n = blockIdx.x * 8 + (tid >> 5);
    if (n >= N_NODES) return;
    const float4* h4 = (const float4*)&g_out1[n * H1];
    float acc = 0.f;
    #pragma unroll 8
    for (int k4 = 0; k4 < H1 / 4; k4++) {
        float4 hv = h4[k4];
        int k = k4 * 4;
        acc += hv.x * Ws[(k + 0) * HID + lane];
        acc += hv.y * Ws[(k + 1) * HID + lane];
        acc += hv.z * Ws[(k + 2) * HID + lane];
        acc += hv.w * Ws[(k + 3) * HID + lane];
    }
    g_xs2[n * HID + lane] = acc;
    float p = acc * a2s[lane];
    #pragma unroll
    for (int off = 16; off; off >>= 1) p += __shfl_down_sync(0xffffffffu, p, off);
    if (lane == 0) g_as2[n] = p;
}

// ---------------- K_edge2a ----------------
__global__ void k_edge2a(const int* __restrict__ ei) {
    int e = blockIdx.x * blockDim.x + threadIdx.x;
    if (e >= N_EDGES) return;
    int src = ei[e], dst = ei[N_EDGES + e];
    float ee = lrelu_exp(g_as2[src] + g_ad2[dst]);
    g_e2[e] = ee;
    atomicAdd(&g_den2[dst], ee);
}

// ---------------- K_scatter2: out2[dst] += xs2[src]*coef  (8 lanes per edge, 32 ch) ----------------
__global__ void k_scatter2(const int* __restrict__ ei) {
    int lane = threadIdx.x & 31;
    int warp = blockIdx.x * 8 + (threadIdx.x >> 5);
    int e = warp * 4 + (lane >> 3);
    if (e >= N_EDGES) return;
    int j = lane & 7;
    int src = ei[e], dst = ei[N_EDGES + e];
    float coef = g_e2[e] / (g_den2[dst] + 1e-16f);
    float4 v = *(const float4*)&g_xs2[src * HID + j * 4];
    v.x *= coef; v.y *= coef; v.z *= coef; v.w *= coef;
    red_add_v4(&g_out2[dst * HID + j * 4], v);
}

// ---------------- K_pred: pred[l] = (out2[a]+b2)·(out2[b]+b2) ----------------
__global__ void k_pred(const int* __restrict__ eli, const float* __restrict__ b2,
                       float* __restrict__ out) {
    int l = blockIdx.x * blockDim.x + threadIdx.x;
    if (l >= N_LABEL) return;
    int a = eli[l], b = eli[N_LABEL + l];
    const float4* pa = (const float4*)&g_out2[a * HID];
    const float4* pb = (const float4*)&g_out2[b * HID];
    const float4* p2 = (const float4*)b2;
    float acc = 0.f;
    #pragma unroll
    for (int i = 0; i < HID / 4; i++) {
        float4 va = pa[i], vb = pb[i], v2 = p2[i];
        acc += (va.x + v2.x) * (vb.x + v2.x);
        acc += (va.y + v2.y) * (vb.y + v2.y);
        acc += (va.z + v2.z) * (vb.z + v2.z);
        acc += (va.w + v2.w) * (vb.w + v2.w);
    }
    out[l] = acc;
}

// ---------------- launch ----------------
extern "C" void kernel_launch(void* const* d_in, const int* in_sizes, int n_in,
                              void* d_out, int out_size) {
    const float* x    = (const float*)d_in[0];
    const int*   ei   = (const int*)  d_in[1];
    const int*   eli  = (const int*)  d_in[2];
    const float* lin_w = (const float*)d_in[3];
    const float* lin_b = (const float*)d_in[4];
    const float* w1s  = (const float*)d_in[5];
    const float* w1d  = (const float*)d_in[6];
    const float* a1s  = (const float*)d_in[7];
    const float* a1d  = (const float*)d_in[8];
    const float* b1   = (const float*)d_in[9];
    const float* w2s  = (const float*)d_in[10];
    const float* w2d  = (const float*)d_in[11];
    const float* a2s  = (const float*)d_in[12];
    const float* a2d  = (const float*)d_in[13];
    const float* b2   = (const float*)d_in[14];
    float* out = (float*)d_out;

    k_zero<<<1024, 256>>>();
    k_prep<<<1, 256>>>(w1d, a1d, w2d, a2d);
    k_lin<<<(N_NODES + 7) / 8, 256>>>(x, lin_w, lin_b);
    k_gemm1<<<(N_NODES + 15) / 16, 256>>>(w1s);
    k_att1<<<(N_NODES + 7) / 8, 256>>>(a1s);
    k_edge1a<<<(N_EDGES + 255) / 256, 256>>>(ei);
    k_scatter1<<<(N_EDGES + 7) / 8, 256>>>(ei);
    k_relu_ad2<<<N_NODES, 256>>>(b1);
    k_gemm2<<<(N_NODES + 7) / 8, 256>>>(w2s, a2s);
    k_edge2a<<<(N_EDGES + 255) / 256, 256>>>(ei);
    k_scatter2<<<(N_EDGES / 4 + 7) / 8, 256>>>(ei);
    k_pred<<<(N_LABEL + 255) / 256, 256>>>(eli, b2, out);
}

// round 2
// speedup vs baseline: 1.1992x; 1.1992x over previous
#include <cuda_runtime.h>

#define N_NODES 50000
#define N_EDGES 800000
#define N_LABEL 200000
#define FEAT 128
#define HID 32
#define HEADS 8
#define H1 256   // HEADS*HID

// ---------------- scratch (device globals; no allocation) ----------------
__device__ __align__(16) float g_h0 [N_NODES * HID];
__device__ __align__(16) float g_xs1[N_NODES * H1];
__device__ __align__(16) float g_as1[N_NODES * HEADS];
__device__ __align__(16) float g_ad1[N_NODES * HEADS];
__device__ __align__(16) float g_out1[N_NODES * H1];   // h1 after relu+bias
__device__ __align__(16) float g_xs2[N_NODES * HID];
__device__ __align__(16) float g_as2[N_NODES];
__device__ __align__(16) float g_ad2[N_NODES];
__device__ __align__(16) float g_out2[N_NODES * HID];  // h2 (+b2 folded)
__device__ __align__(16) float g_v1d[HID * HEADS];
__device__ __align__(16) float g_v2d[H1];
// CSR build
__device__ int g_cnt[N_NODES];
__device__ int g_cur[N_NODES];
__device__ int g_rowptr[N_NODES + 1];
__device__ int g_perm_src[N_EDGES];

__device__ __forceinline__ float lrelu_exp(float a) {
    float l = a > 0.f ? a : 0.2f * a;
    return __expf(l);
}

// ---------------- CSR build ----------------
__global__ void k_zero() {
    int i = blockIdx.x * blockDim.x + threadIdx.x;
    if (i < N_NODES) g_cnt[i] = 0;
}

__global__ void k_hist(const int* __restrict__ ei) {
    int e = blockIdx.x * blockDim.x + threadIdx.x;
    if (e < N_EDGES) atomicAdd(&g_cnt[ei[N_EDGES + e]], 1);
}

// single block, 1024 threads: exclusive scan of g_cnt -> g_rowptr, copy -> g_cur
__global__ void k_scan() {
    __shared__ int sums[1024];
    int tid = threadIdx.x;
    const int CH = (N_NODES + 1023) / 1024;  // 49
    int base = tid * CH;
    int s = 0;
    for (int i = 0; i < CH; i++) {
        int idx = base + i;
        if (idx < N_NODES) s += g_cnt[idx];
    }
    sums[tid] = s;
    __syncthreads();
    for (int off = 1; off < 1024; off <<= 1) {
        int v = (tid >= off) ? sums[tid - off] : 0;
        __syncthreads();
        sums[tid] += v;
        __syncthreads();
    }
    int run = (tid == 0) ? 0 : sums[tid - 1];
    for (int i = 0; i < CH; i++) {
        int idx = base + i;
        if (idx < N_NODES) {
            g_rowptr[idx] = run;
            g_cur[idx] = run;
            run += g_cnt[idx];
        }
    }
    if (tid == 1023) g_rowptr[N_NODES] = run;
}

__global__ void k_permute(const int* __restrict__ ei) {
    int e = blockIdx.x * blockDim.x + threadIdx.x;
    if (e >= N_EDGES) return;
    int src = ei[e], dst = ei[N_EDGES + e];
    int pos = atomicAdd(&g_cur[dst], 1);
    g_perm_src[pos] = src;
}

// ---------------- K_prep: fold dst projections with attention vectors ----------------
__global__ void k_prep(const float* __restrict__ w1d, const float* __restrict__ a1d,
                       const float* __restrict__ w2d, const float* __restrict__ a2d) {
    int tid = threadIdx.x;  // 256
    {
        int k = tid >> 3, h = tid & 7;
        float s = 0.f;
        #pragma unroll
        for (int c = 0; c < HID; c++) s += w1d[k * H1 + h * HID + c] * a1d[h * HID + c];
        g_v1d[k * HEADS + h] = s;
    }
    {
        int k = tid;
        float s = 0.f;
        #pragma unroll
        for (int c = 0; c < HID; c++) s += w2d[k * HID + c] * a2d[c];
        g_v2d[k] = s;
    }
}

// ---------------- K_lin: h0 = x @ lin_w + lin_b, fused ad1 ----------------
__global__ void k_lin(const float* __restrict__ x, const float* __restrict__ w,
                      const float* __restrict__ b) {
    __shared__ float Ws[FEAT * HID];
    __shared__ float Xs[8 * FEAT];
    int tid = threadIdx.x;  // 256
    for (int i = tid; i < FEAT * HID; i += 256) Ws[i] = w[i];
    int nb = blockIdx.x * 8;
    for (int i = tid; i < 8 * FEAT; i += 256) {
        int n = nb + (i >> 7);
        Xs[i] = (n < N_NODES) ? x[(long long)n * FEAT + (i & 127)] : 0.f;
    }
    __syncthreads();
    int c = tid & 31, i = tid >> 5;
    int n = nb + i;
    if (n >= N_NODES) return;
    float acc = b[c];
    const float4* xr = (const float4*)&Xs[i * FEAT];
    #pragma unroll
    for (int k4 = 0; k4 < FEAT / 4; k4++) {
        float4 xv = xr[k4];
        int k = k4 * 4;
        acc += xv.x * Ws[(k + 0) * HID + c];
        acc += xv.y * Ws[(k + 1) * HID + c];
        acc += xv.z * Ws[(k + 2) * HID + c];
        acc += xv.w * Ws[(k + 3) * HID + c];
    }
    g_h0[n * HID + c] = acc;
    // ad1[n,h] = sum_c h0[n,c] * v1d[c,h]
    #pragma unroll
    for (int h = 0; h < HEADS; h++) {
        float d = acc * g_v1d[c * HEADS + h];
        #pragma unroll
        for (int off = 16; off; off >>= 1) d += __shfl_down_sync(0xffffffffu, d, off);
        if (c == 0) g_ad1[n * HEADS + h] = d;
    }
}

// ---------------- K_gemm1: xs1 = h0 @ w1s, fused as1 ----------------
__global__ void k_gemm1(const float* __restrict__ w1s, const float* __restrict__ a1s) {
    __shared__ float Hs[16 * HID];
    int tid = threadIdx.x;  // 256: one output column per thread
    float wreg[HID];
    #pragma unroll
    for (int k = 0; k < HID; k++) wreg[k] = w1s[k * H1 + tid];
    float av = a1s[tid];  // a1s[h*HID+c] with h=tid>>5, c=tid&31
    int nb = blockIdx.x * 16;
    for (int i = tid; i < 16 * HID; i += 256) {
        int n = nb + (i >> 5);
        Hs[i] = (n < N_NODES) ? g_h0[n * HID + (i & 31)] : 0.f;
    }
    __syncthreads();
    int lane = tid & 31, h = tid >> 5;
    #pragma unroll 4
    for (int i = 0; i < 16; i++) {
        int n = nb + i;
        if (n >= N_NODES) break;
        const float4* hr = (const float4*)&Hs[i * HID];
        float acc = 0.f;
        #pragma unroll
        for (int k4 = 0; k4 < HID / 4; k4++) {
            float4 hv = hr[k4];
            int k = k4 * 4;
            acc += hv.x * wreg[k + 0];
            acc += hv.y * wreg[k + 1];
            acc += hv.z * wreg[k + 2];
            acc += hv.w * wreg[k + 3];
        }
        g_xs1[n * H1 + tid] = acc;
        float p = acc * av;
        #pragma unroll
        for (int off = 16; off; off >>= 1) p += __shfl_down_sync(0xffffffffu, p, off);
        if (lane == 0) g_as1[n * HEADS + h] = p;
    }
}

// ---------------- K_agg1: CSR gather aggregation for conv1, fused relu+b1 and ad2 ----------------
__global__ void k_agg1(const float* __restrict__ b1) {
    int lane = threadIdx.x & 31;
    int n = blockIdx.x * 8 + (threadIdx.x >> 5);
    if (n >= N_NODES) return;
    int beg = g_rowptr[n], end = g_rowptr[n + 1];
    float adh[8];
    {
        float4 t0 = *(const float4*)&g_ad1[n * 8];
        float4 t1 = *(const float4*)&g_ad1[n * 8 + 4];
        adh[0] = t0.x; adh[1] = t0.y; adh[2] = t0.z; adh[3] = t0.w;
        adh[4] = t1.x; adh[5] = t1.y; adh[6] = t1.z; adh[7] = t1.w;
    }
    // pass A: denominators
    float den[8] = {0, 0, 0, 0, 0, 0, 0, 0};
    for (int p = beg + lane; p < end; p += 32) {
        int src = __ldg(&g_perm_src[p]);
        float4 s0 = *(const float4*)&g_as1[src * 8];
        float4 s1 = *(const float4*)&g_as1[src * 8 + 4];
        den[0] += lrelu_exp(s0.x + adh[0]);
        den[1] += lrelu_exp(s0.y + adh[1]);
        den[2] += lrelu_exp(s0.z + adh[2]);
        den[3] += lrelu_exp(s0.w + adh[3]);
        den[4] += lrelu_exp(s1.x + adh[4]);
        den[5] += lrelu_exp(s1.y + adh[5]);
        den[6] += lrelu_exp(s1.z + adh[6]);
        den[7] += lrelu_exp(s1.w + adh[7]);
    }
    #pragma unroll
    for (int h = 0; h < 8; h++) {
        float v = den[h];
        #pragma unroll
        for (int off = 16; off; off >>= 1) v += __shfl_xor_sync(0xffffffffu, v, off);
        den[h] = 1.0f / (v + 1e-16f);
    }
    // pass B: weighted gather. lane covers channels [lane*8, lane*8+8) -> head lane>>2
    int cb = lane * 8;
    int hh = lane >> 2;
    float myad = adh[hh];
    float rden = den[hh];
    float4 accA = {0, 0, 0, 0}, accB = {0, 0, 0, 0};
    for (int p = beg; p < end; p++) {
        int src = __ldg(&g_perm_src[p]);
        float as = g_as1[src * 8 + hh];
        float coef = lrelu_exp(as + myad) * rden;
        const float4* xp = (const float4*)&g_xs1[src * H1 + cb];
        float4 vA = xp[0], vB = xp[1];
        accA.x += vA.x * coef; accA.y += vA.y * coef;
        accA.z += vA.z * coef; accA.w += vA.w * coef;
        accB.x += vB.x * coef; accB.y += vB.y * coef;
        accB.z += vB.z * coef; accB.w += vB.w * coef;
    }
    // epilogue: h1 = relu(acc + b1); ad2 = h1 . v2d
    float4 bA = *(const float4*)&b1[cb], bB = *(const float4*)&b1[cb + 4];
    float4 hA, hB;
    hA.x = fmaxf(accA.x + bA.x, 0.f); hA.y = fmaxf(accA.y + bA.y, 0.f);
    hA.z = fmaxf(accA.z + bA.z, 0.f); hA.w = fmaxf(accA.w + bA.w, 0.f);
    hB.x = fmaxf(accB.x + bB.x, 0.f); hB.y = fmaxf(accB.y + bB.y, 0.f);
    hB.z = fmaxf(accB.z + bB.z, 0.f); hB.w = fmaxf(accB.w + bB.w, 0.f);
    *(float4*)&g_out1[n * H1 + cb] = hA;
    *(float4*)&g_out1[n * H1 + cb + 4] = hB;
    float4 vA = *(const float4*)&g_v2d[cb], vB = *(const float4*)&g_v2d[cb + 4];
    float pd = hA.x * vA.x + hA.y * vA.y + hA.z * vA.z + hA.w * vA.w
             + hB.x * vB.x + hB.y * vB.y + hB.z * vB.z + hB.w * vB.w;
    #pragma unroll
    for (int off = 16; off; off >>= 1) pd += __shfl_down_sync(0xffffffffu, pd, off);
    if (lane == 0) g_ad2[n] = pd;
}

// ---------------- K_gemm2: xs2 = h1 @ w2s, fused as2 ----------------
__global__ void k_gemm2(const float* __restrict__ w2s, const float* __restrict__ a2s) {
    __shared__ float Ws[H1 * HID];  // 32KB
    int tid = threadIdx.x;  // 256
    for (int i = tid; i < H1 * HID; i += 256) Ws[i] = w2s[i];
    __syncthreads();
    int lane = tid & 31;
    int n = blockIdx.x * 8 + (tid >> 5);
    if (n >= N_NODES) return;
    const float4* h4 = (const float4*)&g_out1[n * H1];
    float acc = 0.f;
    #pragma unroll 8
    for (int k4 = 0; k4 < H1 / 4; k4++) {
        float4 hv = h4[k4];
        int k = k4 * 4;
        acc += hv.x * Ws[(k + 0) * HID + lane];
        acc += hv.y * Ws[(k + 1) * HID + lane];
        acc += hv.z * Ws[(k + 2) * HID + lane];
        acc += hv.w * Ws[(k + 3) * HID + lane];
    }
    g_xs2[n * HID + lane] = acc;
    float p = acc * a2s[lane];
    #pragma unroll
    for (int off = 16; off; off >>= 1) p += __shfl_down_sync(0xffffffffu, p, off);
    if (lane == 0) g_as2[n] = p;
}

// ---------------- K_agg2: CSR gather aggregation for conv2 (+b2 folded) ----------------
__global__ void k_agg2(const float* __restrict__ b2) {
    int lane = threadIdx.x & 31;
    int n = blockIdx.x * 8 + (threadIdx.x >> 5);
    if (n >= N_NODES) return;
    int beg = g_rowptr[n], end = g_rowptr[n + 1];
    float adn = g_ad2[n];
    float den = 0.f;
    for (int p = beg + lane; p < end; p += 32)
        den += lrelu_exp(g_as2[__ldg(&g_perm_src[p])] + adn);
    #pragma unroll
    for (int off = 16; off; off >>= 1) den += __shfl_xor_sync(0xffffffffu, den, off);
    float rden = 1.0f / (den + 1e-16f);
    // 4 edges in parallel: lane = k*8 + j, edge group k, channels j*4..j*4+3
    int k = lane >> 3, j = lane & 7;
    float4 acc = {0, 0, 0, 0};
    for (int p = beg + k; p < end; p += 4) {
        int src = __ldg(&g_perm_src[p]);
        float coef = lrelu_exp(g_as2[src] + adn) * rden;
        float4 v = *(const float4*)&g_xs2[src * HID + j * 4];
        acc.x += v.x * coef; acc.y += v.y * coef;
        acc.z += v.z * coef; acc.w += v.w * coef;
    }
    acc.x += __shfl_xor_sync(0xffffffffu, acc.x, 8);
    acc.y += __shfl_xor_sync(0xffffffffu, acc.y, 8);
    acc.z += __shfl_xor_sync(0xffffffffu, acc.z, 8);
    acc.w += __shfl_xor_sync(0xffffffffu, acc.w, 8);
    acc.x += __shfl_xor_sync(0xffffffffu, acc.x, 16);
    acc.y += __shfl_xor_sync(0xffffffffu, acc.y, 16);
    acc.z += __shfl_xor_sync(0xffffffffu, acc.z, 16);
    acc.w += __shfl_xor_sync(0xffffffffu, acc.w, 16);
    if (lane < 8) {
        float4 bb = *(const float4*)&b2[j * 4];
        acc.x += bb.x; acc.y += bb.y; acc.z += bb.z; acc.w += bb.w;
        *(float4*)&g_out2[n * HID + j * 4] = acc;
    }
}

// ---------------- K_pred ----------------
__global__ void k_pred(const int* __restrict__ eli, float* __restrict__ out) {
    int l = blockIdx.x * blockDim.x + threadIdx.x;
    if (l >= N_LABEL) return;
    int a = eli[l], b = eli[N_LABEL + l];
    const float4* pa = (const float4*)&g_out2[a * HID];
    const float4* pb = (const float4*)&g_out2[b * HID];
    float acc = 0.f;
    #pragma unroll
    for (int i = 0; i < HID / 4; i++) {
        float4 va = pa[i], vb = pb[i];
        acc += va.x * vb.x + va.y * vb.y + va.z * vb.z + va.w * vb.w;
    }
    out[l] = acc;
}

// ---------------- launch ----------------
extern "C" void kernel_launch(void* const* d_in, const int* in_sizes, int n_in,
                              void* d_out, int out_size) {
    const float* x     = (const float*)d_in[0];
    const int*   ei    = (const int*)  d_in[1];
    const int*   eli   = (const int*)  d_in[2];
    const float* lin_w = (const float*)d_in[3];
    const float* lin_b = (const float*)d_in[4];
    const float* w1s   = (const float*)d_in[5];
    const float* w1d   = (const float*)d_in[6];
    const float* a1s   = (const float*)d_in[7];
    const float* a1d   = (const float*)d_in[8];
    const float* b1    = (const float*)d_in[9];
    const float* w2s   = (const float*)d_in[10];
    const float* w2d   = (const float*)d_in[11];
    const float* a2s   = (const float*)d_in[12];
    const float* a2d   = (const float*)d_in[13];
    const float* b2    = (const float*)d_in[14];
    float* out = (float*)d_out;

    k_zero<<<(N_NODES + 1023) / 1024, 1024>>>();
    k_hist<<<(N_EDGES + 255) / 256, 256>>>(ei);
    k_scan<<<1, 1024>>>();
    k_permute<<<(N_EDGES + 255) / 256, 256>>>(ei);
    k_prep<<<1, 256>>>(w1d, a1d, w2d, a2d);
    k_lin<<<(N_NODES + 7) / 8, 256>>>(x, lin_w, lin_b);
    k_gemm1<<<(N_NODES + 15) / 16, 256>>>(w1s, a1s);
    k_agg1<<<(N_NODES + 7) / 8, 256>>>(b1);
    k_gemm2<<<(N_NODES + 7) / 8, 256>>>(w2s, a2s);
    k_agg2<<<(N_NODES + 7) / 8, 256>>>(b2);
    k_pred<<<(N_LABEL + 255) / 256, 256>>>(eli, out);
}